// round 1
// baseline (speedup 1.0000x reference)
#include <cuda_runtime.h>
#include <cuda_bf16.h>

#define NJ 24
#define EPSF 1e-6f

// Shared layout per joint (6 float4 = 24 floats):
//  [0] m00 m01 m02 m03      (transform row 0)
//  [1] m10 m11 m12 m13      (row 1)
//  [2] m20 m21 m22 m23      (row 2)
//  [3] lx  ly  lz  a0       (loc, SH const term incl. +0.5)
//  [4] a1  a2  a3  a4       (y, z, x, xy coefficients)
//  [5] a5  a6  a7  a8       (yz, 2zz-xx-yy, xz, xx-yy coefficients)

__global__ __launch_bounds__(256)
void shCaster_kernel(const float* __restrict__ xyz,
                     const float* __restrict__ vdir,
                     const float* __restrict__ transforms,
                     const float* __restrict__ sh_feats,
                     const float* __restrict__ locs,
                     float* __restrict__ out,
                     int n)
{
    __shared__ float4 S[NJ * 6];

    {
        float* Sf = reinterpret_cast<float*>(S);
        const float coef0 = 0.28209479177387814f;
        const float coefA = 0.4886025119029199f;   // C1
        const float coefB = 1.0925484305920792f;   // |C2[0,1,3]|
        const float coefC = 0.31539156525252005f;  // C2[2]
        const float coefD = 0.5462742152960396f;   // C2[4]
        for (int idx = threadIdx.x; idx < NJ * 24; idx += blockDim.x) {
            int j = idx / 24, k = idx % 24;
            float v;
            if (k < 12) {
                v = transforms[j * 16 + k];            // rows 0..2 of 4x4
            } else if (k < 15) {
                v = locs[j * 3 + (k - 12)];
            } else {
                int s = k - 15;
                float f = sh_feats[j * 9 + s];
                float c;
                switch (s) {
                    case 0: c = coef0; break;
                    case 1: c = -coefA; break;
                    case 2: c =  coefA; break;
                    case 3: c = -coefA; break;
                    case 4: c =  coefB; break;
                    case 5: c = -coefB; break;
                    case 6: c =  coefC; break;
                    case 7: c = -coefB; break;
                    default: c = coefD; break;
                }
                v = c * f;
                if (s == 0) v += 0.5f;                  // fold rads' +0.5
            }
            Sf[j * 24 + k] = v;
        }
    }
    __syncthreads();

    int i = blockIdx.x * blockDim.x + threadIdx.x;
    if (i >= n) return;

    const float x  = __ldg(&xyz[3 * i]);
    const float y  = __ldg(&xyz[3 * i + 1]);
    const float z  = __ldg(&xyz[3 * i + 2]);
    const float vx = __ldg(&vdir[3 * i]);
    const float vy = __ldg(&vdir[3 * i + 1]);
    const float vz = __ldg(&vdir[3 * i + 2]);

    float wsum = 0.f;
    float ox = 0.f, oy = 0.f, oz = 0.f;   // sum w * pts
    float rx = 0.f, ry = 0.f, rz = 0.f;   // sum w * (R @ viewdir)

#pragma unroll
    for (int j = 0; j < NJ; ++j) {
        const float4 m0  = S[j * 6 + 0];
        const float4 m1  = S[j * 6 + 1];
        const float4 m2  = S[j * 6 + 2];
        const float4 lc  = S[j * 6 + 3];
        const float4 a14 = S[j * 6 + 4];
        const float4 a58 = S[j * 6 + 5];

        // pts_j = (M_j @ [x,1])[:3]   (shared between SH step and output blend)
        float px = fmaf(m0.x, x, fmaf(m0.y, y, fmaf(m0.z, z, m0.w)));
        float py = fmaf(m1.x, x, fmaf(m1.y, y, fmaf(m1.z, z, m1.w)));
        float pz = fmaf(m2.x, x, fmaf(m2.y, y, fmaf(m2.z, z, m2.w)));

        // R_j @ viewdir  (homogeneous parts of xyz/view branches cancel)
        float Rx = fmaf(m0.x, vx, fmaf(m0.y, vy, m0.z * vz));
        float Ry = fmaf(m1.x, vx, fmaf(m1.y, vy, m1.z * vz));
        float Rz = fmaf(m2.x, vx, fmaf(m2.y, vy, m2.z * vz));

        // direction loc - pts, length, unit vector
        float dx = lc.x - px, dy = lc.y - py, dz = lc.z - pz;
        float n2 = fmaf(dx, dx, fmaf(dy, dy, dz * dz));
        float invn = rsqrtf(fmaxf(n2, 1e-24f));
        float len = n2 * invn;
        float ux = dx * invn, uy = dy * invn, uz = dz * invn;

        // SH radius: a0 + a1*y + a2*z + a3*x + a4*xy + a5*yz
        //            + a6*(2zz-xx-yy) + a7*xz + a8*(xx-yy), then relu
        float xx = ux * ux, yy = uy * uy, zz = uz * uz;
        float rad = lc.w;
        rad = fmaf(a14.x, uy, rad);
        rad = fmaf(a14.y, uz, rad);
        rad = fmaf(a14.z, ux, rad);
        rad = fmaf(a14.w, ux * uy, rad);
        rad = fmaf(a58.x, uy * uz, rad);
        rad = fmaf(a58.y, fmaf(2.f, zz, -(xx + yy)), rad);
        rad = fmaf(a58.z, ux * uz, rad);
        rad = fmaf(a58.w, xx - yy, rad);
        rad = fmaxf(rad, 0.f);

        // rel = relu(1 - len/rad), forced 0 when rad < EPS
        float w = fmaxf(1.f - len * __fdividef(1.f, rad), 0.f);
        w = (rad >= EPSF) ? w : 0.f;

        wsum += w;
        ox = fmaf(w, px, ox); oy = fmaf(w, py, oy); oz = fmaf(w, pz, oz);
        rx = fmaf(w, Rx, rx); ry = fmaf(w, Ry, ry); rz = fmaf(w, Rz, rz);
    }

    float oxo, oyo, ozo, wxo, wyo, wzo;
    if (wsum > EPSF) {
        float inv = 1.f / wsum;
        oxo = ox * inv; oyo = oy * inv; ozo = oz * inv;
        wxo = rx * inv; wyo = ry * inv; wzo = rz * inv;
    } else {
        oxo = x;  oyo = y;  ozo = z;
        wxo = vx; wyo = vy; wzo = vz;
    }

    out[3 * i]     = oxo;
    out[3 * i + 1] = oyo;
    out[3 * i + 2] = ozo;
    float* out2 = out + (size_t)3 * n;
    out2[3 * i]     = wxo;
    out2[3 * i + 1] = wyo;
    out2[3 * i + 2] = wzo;
}

extern "C" void kernel_launch(void* const* d_in, const int* in_sizes, int n_in,
                              void* d_out, int out_size) {
    const float* xyz        = (const float*)d_in[0];  // (4096,128,3) f32
    const float* viewdirs   = (const float*)d_in[1];  // (4096,128,3) f32
    const float* transforms = (const float*)d_in[2];  // (24,4,4) f32
    // d_in[3] = ray_valid (bool) — unused by the reference computation
    const float* sh_feats   = (const float*)d_in[4];  // (24,9) f32
    const float* locs       = (const float*)d_in[5];  // (24,3) f32
    float* out = (float*)d_out;                       // [xyz_out | view_out]

    int n = in_sizes[0] / 3;                          // 524288 points
    int threads = 256;
    int blocks = (n + threads - 1) / threads;
    shCaster_kernel<<<blocks, threads>>>(xyz, viewdirs, transforms, sh_feats,
                                         locs, out, n);
}

// round 3
// speedup vs baseline: 1.1174x; 1.1174x over previous
#include <cuda_runtime.h>
#include <cuda_bf16.h>

#define NJ 24
#define EPSF 1e-6f

typedef unsigned long long ull;

// ---- packed f32x2 helpers (Blackwell sm_103a) ----
__device__ __forceinline__ ull f2_fma(ull a, ull b, ull c) {
    ull d; asm("fma.rn.f32x2 %0, %1, %2, %3;" : "=l"(d) : "l"(a), "l"(b), "l"(c)); return d;
}
__device__ __forceinline__ ull f2_mul(ull a, ull b) {
    ull d; asm("mul.rn.f32x2 %0, %1, %2;" : "=l"(d) : "l"(a), "l"(b)); return d;
}
__device__ __forceinline__ ull f2_add(ull a, ull b) {
    ull d; asm("add.rn.f32x2 %0, %1, %2;" : "=l"(d) : "l"(a), "l"(b)); return d;
}
__device__ __forceinline__ ull f2_pack(float lo, float hi) {
    ull d;
    asm("mov.b64 %0, {%1, %2};" : "=l"(d) : "r"(__float_as_uint(lo)), "r"(__float_as_uint(hi)));
    return d;
}
__device__ __forceinline__ void f2_unpack(ull a, float& lo, float& hi) {
    unsigned int l, h;
    asm("mov.b64 {%0, %1}, %2;" : "=r"(l), "=r"(h) : "l"(a));
    lo = __uint_as_float(l); hi = __uint_as_float(h);
}
__device__ __forceinline__ float rsq_ap(float x) {
    float r; asm("rsqrt.approx.f32 %0, %1;" : "=f"(r) : "f"(x)); return r;
}
__device__ __forceinline__ float rcp_ap(float x) {
    float r; asm("rcp.approx.f32 %0, %1;" : "=f"(r) : "f"(x)); return r;
}

// Shared: per joint, 24 constants each duplicated into a 64-bit {c,c} pair.
// k: 0..11 = transform rows 0..2 (m00..m23), 12..14 = loc, 15 = a0 (+0.5 folded),
// 16..23 = a1..a8 (SH coefficients pre-multiplied by feats).

__global__ __launch_bounds__(256)
void shCaster_kernel(const float* __restrict__ xyz,
                     const float* __restrict__ vdir,
                     const float* __restrict__ transforms,
                     const float* __restrict__ sh_feats,
                     const float* __restrict__ locs,
                     float* __restrict__ out,
                     int half, int n)
{
    __shared__ __align__(16) ull S2[NJ * 24];

    {
        const float coef0 = 0.28209479177387814f;
        const float coefA = 0.4886025119029199f;
        const float coefB = 1.0925484305920792f;
        const float coefC = 0.31539156525252005f;
        const float coefD = 0.5462742152960396f;
        for (int idx = threadIdx.x; idx < NJ * 24; idx += blockDim.x) {
            int j = idx / 24, k = idx % 24;
            float v;
            if (k < 12) {
                v = transforms[j * 16 + k];
            } else if (k < 15) {
                v = locs[j * 3 + (k - 12)];
            } else {
                int s = k - 15;
                float f = sh_feats[j * 9 + s];
                float c;
                switch (s) {
                    case 0: c = coef0; break;
                    case 1: c = -coefA; break;
                    case 2: c =  coefA; break;
                    case 3: c = -coefA; break;
                    case 4: c =  coefB; break;
                    case 5: c = -coefB; break;
                    case 6: c =  coefC; break;
                    case 7: c = -coefB; break;
                    default: c = coefD; break;
                }
                v = c * f;
                if (s == 0) v += 0.5f;
            }
            unsigned int b = __float_as_uint(v);
            S2[j * 24 + k] = ((ull)b << 32) | b;   // duplicated pair {v, v}
        }
    }
    __syncthreads();

    int t = blockIdx.x * blockDim.x + threadIdx.x;
    if (t >= half) return;
    int i0 = t, i1 = t + half;

    // Two points per thread, packed lane-wise.
    const ull x2  = f2_pack(__ldg(&xyz[3 * i0]),     __ldg(&xyz[3 * i1]));
    const ull y2  = f2_pack(__ldg(&xyz[3 * i0 + 1]), __ldg(&xyz[3 * i1 + 1]));
    const ull z2  = f2_pack(__ldg(&xyz[3 * i0 + 2]), __ldg(&xyz[3 * i1 + 2]));
    const ull vx2 = f2_pack(__ldg(&vdir[3 * i0]),     __ldg(&vdir[3 * i1]));
    const ull vy2 = f2_pack(__ldg(&vdir[3 * i0 + 1]), __ldg(&vdir[3 * i1 + 1]));
    const ull vz2 = f2_pack(__ldg(&vdir[3 * i0 + 2]), __ldg(&vdir[3 * i1 + 2]));

    const ull NEG1  = f2_pack(-1.f, -1.f);
    const ull THREE = f2_pack(3.f, 3.f);

    ull wsum2 = 0ull;
    ull ox2 = 0ull, oy2 = 0ull, oz2 = 0ull;
    ull rx2 = 0ull, ry2 = 0ull, rz2 = 0ull;

#pragma unroll
    for (int j = 0; j < NJ; ++j) {
        const ulonglong2* C = reinterpret_cast<const ulonglong2*>(S2 + j * 24);
        const ulonglong2 c0 = C[0];   // m00 m01
        const ulonglong2 c1 = C[1];   // m02 m03
        const ulonglong2 c2 = C[2];   // m10 m11
        const ulonglong2 c3 = C[3];   // m12 m13
        const ulonglong2 c4 = C[4];   // m20 m21
        const ulonglong2 c5 = C[5];   // m22 m23
        const ulonglong2 c6 = C[6];   // lx  ly
        const ulonglong2 c7 = C[7];   // lz  a0
        const ulonglong2 c8 = C[8];   // a1  a2
        const ulonglong2 c9 = C[9];   // a3  a4
        const ulonglong2 cA = C[10];  // a5  a6
        const ulonglong2 cB = C[11];  // a7  a8

        // pts_j = (M_j @ [p,1])[:3]
        ull px2 = f2_fma(c0.x, x2, f2_fma(c0.y, y2, f2_fma(c1.x, z2, c1.y)));
        ull py2 = f2_fma(c2.x, x2, f2_fma(c2.y, y2, f2_fma(c3.x, z2, c3.y)));
        ull pz2 = f2_fma(c4.x, x2, f2_fma(c4.y, y2, f2_fma(c5.x, z2, c5.y)));

        // R_j @ viewdir (homogeneous parts cancel between branches)
        ull Rx2 = f2_fma(c0.x, vx2, f2_fma(c0.y, vy2, f2_mul(c1.x, vz2)));
        ull Ry2 = f2_fma(c2.x, vx2, f2_fma(c2.y, vy2, f2_mul(c3.x, vz2)));
        ull Rz2 = f2_fma(c4.x, vx2, f2_fma(c4.y, vy2, f2_mul(c5.x, vz2)));

        // d = loc - pts ; n2 = |d|^2
        ull dx2 = f2_fma(px2, NEG1, c6.x);
        ull dy2 = f2_fma(py2, NEG1, c6.y);
        ull dz2 = f2_fma(pz2, NEG1, c7.x);
        ull n22 = f2_fma(dx2, dx2, f2_fma(dy2, dy2, f2_mul(dz2, dz2)));

        // per-lane clamp + rsqrt
        float n2a, n2b; f2_unpack(n22, n2a, n2b);
        n2a = fmaxf(n2a, 1e-24f); n2b = fmaxf(n2b, 1e-24f);
        float ia = rsq_ap(n2a), ib = rsq_ap(n2b);
        ull inv2 = f2_pack(ia, ib);
        ull n2c  = f2_pack(n2a, n2b);

        ull len2 = f2_mul(n2c, inv2);                 // |d|
        ull ux2 = f2_mul(dx2, inv2);
        ull uy2 = f2_mul(dy2, inv2);
        ull uz2 = f2_mul(dz2, inv2);

        ull xx2 = f2_mul(ux2, ux2);
        ull yy2 = f2_mul(uy2, uy2);
        ull zz2 = f2_mul(uz2, uz2);

        // rad = a0 + a1*y + a2*z + a3*x + a4*xy + a5*yz + a6*(3zz-1) + a7*xz + a8*(xx-yy)
        ull rad2 = c7.y;
        rad2 = f2_fma(c8.x, uy2, rad2);
        rad2 = f2_fma(c8.y, uz2, rad2);
        rad2 = f2_fma(c9.x, ux2, rad2);
        rad2 = f2_fma(c9.y, f2_mul(ux2, uy2), rad2);
        rad2 = f2_fma(cA.x, f2_mul(uy2, uz2), rad2);
        rad2 = f2_fma(cA.y, f2_fma(zz2, THREE, NEG1), rad2);   // 2zz-xx-yy on unit u
        rad2 = f2_fma(cB.x, f2_mul(ux2, uz2), rad2);
        rad2 = f2_fma(cB.y, f2_fma(yy2, NEG1, xx2), rad2);

        // per-lane: relu(rad), w = relu(1 - len/rad), zero when rad < EPS
        float ra, rb; f2_unpack(rad2, ra, rb);
        float la, lb; f2_unpack(len2, la, lb);
        ra = fmaxf(ra, 0.f); rb = fmaxf(rb, 0.f);
        float wa = fmaxf(fmaf(-la, rcp_ap(ra), 1.f), 0.f);
        float wb = fmaxf(fmaf(-lb, rcp_ap(rb), 1.f), 0.f);
        wa = (ra >= EPSF) ? wa : 0.f;
        wb = (rb >= EPSF) ? wb : 0.f;
        ull w2 = f2_pack(wa, wb);

        wsum2 = f2_add(wsum2, w2);
        ox2 = f2_fma(w2, px2, ox2);
        oy2 = f2_fma(w2, py2, oy2);
        oz2 = f2_fma(w2, pz2, oz2);
        rx2 = f2_fma(w2, Rx2, rx2);
        ry2 = f2_fma(w2, Ry2, ry2);
        rz2 = f2_fma(w2, Rz2, rz2);
    }

    // Epilogue per lane
    float wsa, wsb;  f2_unpack(wsum2, wsa, wsb);
    float oxa, oxb;  f2_unpack(ox2, oxa, oxb);
    float oya, oyb;  f2_unpack(oy2, oya, oyb);
    float oza, ozb;  f2_unpack(oz2, oza, ozb);
    float rxa, rxb;  f2_unpack(rx2, rxa, rxb);
    float rya, ryb;  f2_unpack(ry2, rya, ryb);
    float rza, rzb;  f2_unpack(rz2, rza, rzb);

    float xa, xb, ya, yb, za, zb, vxa, vxb, vya, vyb, vza, vzb;
    f2_unpack(x2, xa, xb);   f2_unpack(y2, ya, yb);   f2_unpack(z2, za, zb);
    f2_unpack(vx2, vxa, vxb); f2_unpack(vy2, vya, vyb); f2_unpack(vz2, vza, vzb);

    float* out2 = out + (size_t)3 * n;

    if (wsa > EPSF) {
        float inv = rcp_ap(wsa);
        out[3 * i0] = oxa * inv;  out[3 * i0 + 1] = oya * inv;  out[3 * i0 + 2] = oza * inv;
        out2[3 * i0] = rxa * inv; out2[3 * i0 + 1] = rya * inv; out2[3 * i0 + 2] = rza * inv;
    } else {
        out[3 * i0] = xa;  out[3 * i0 + 1] = ya;  out[3 * i0 + 2] = za;
        out2[3 * i0] = vxa; out2[3 * i0 + 1] = vya; out2[3 * i0 + 2] = vza;
    }
    if (wsb > EPSF) {
        float inv = rcp_ap(wsb);
        out[3 * i1] = oxb * inv;  out[3 * i1 + 1] = oyb * inv;  out[3 * i1 + 2] = ozb * inv;
        out2[3 * i1] = rxb * inv; out2[3 * i1 + 1] = ryb * inv; out2[3 * i1 + 2] = rzb * inv;
    } else {
        out[3 * i1] = xb;  out[3 * i1 + 1] = yb;  out[3 * i1 + 2] = zb;
        out2[3 * i1] = vxb; out2[3 * i1 + 1] = vyb; out2[3 * i1 + 2] = vzb;
    }
}

extern "C" void kernel_launch(void* const* d_in, const int* in_sizes, int n_in,
                              void* d_out, int out_size) {
    const float* xyz        = (const float*)d_in[0];
    const float* viewdirs   = (const float*)d_in[1];
    const float* transforms = (const float*)d_in[2];
    // d_in[3] = ray_valid — unused
    const float* sh_feats   = (const float*)d_in[4];
    const float* locs       = (const float*)d_in[5];
    float* out = (float*)d_out;

    int n = in_sizes[0] / 3;      // 524288
    int half = n / 2;             // 262144, n is even
    int threads = 256;
    int blocks = (half + threads - 1) / threads;
    shCaster_kernel<<<blocks, threads>>>(xyz, viewdirs, transforms, sh_feats,
                                         locs, out, half, n);
}